// round 3
// baseline (speedup 1.0000x reference)
#include <cuda_runtime.h>
#include <cuda_bf16.h>
#include <math.h>

#define N_MAX   100000
#define E_MAX   3300000
#define IN_CH   512
#define H1F     64      // heads1*ch1
#define OUT_CH  16

// ---------------- device scratch (no allocation allowed) ----------------
__device__ float g_h1  [(size_t)N_MAX * H1F];    // x@W1
__device__ float g_e1s [(size_t)N_MAX * 8];
__device__ float g_e1d [(size_t)N_MAX * 8];
__device__ float g_hact[(size_t)N_MAX * H1F];    // elu(layer1 out)
__device__ float g_h2  [(size_t)N_MAX * OUT_CH]; // hact@W2
__device__ float g_e2s [N_MAX];
__device__ float g_e2d [N_MAX];
__device__ int   g_deg [N_MAX];
__device__ int   g_off [N_MAX + 1];
__device__ int   g_cur [N_MAX];
__device__ int   g_csr [E_MAX];
__device__ int   g_bsum[128];

// ---------------- CSR build ----------------
__global__ void k_zero(int N) {
    int i = blockIdx.x * blockDim.x + threadIdx.x;
    if (i < N) g_deg[i] = 0;
}

__global__ void k_deg(const int* __restrict__ ei, int E_orig, int E_tot) {
    int i = blockIdx.x * blockDim.x + threadIdx.x;
    if (i >= E_tot) return;
    int dst = (i < E_orig) ? ei[E_orig + i] : (i - E_orig);
    atomicAdd(&g_deg[dst], 1);
}

__global__ void k_scanA(int N) {      // grid: ceil(N/1024), block 1024
    __shared__ int s[1024];
    int tid = threadIdx.x;
    int i = blockIdx.x * 1024 + tid;
    int v = (i < N) ? g_deg[i] : 0;
    s[tid] = v;
    __syncthreads();
    for (int o = 1; o < 1024; o <<= 1) {
        int t = (tid >= o) ? s[tid - o] : 0;
        __syncthreads();
        s[tid] += t;
        __syncthreads();
    }
    if (i < N) g_off[i + 1] = s[tid];
    if (tid == 1023) g_bsum[blockIdx.x] = s[1023];
}

__global__ void k_scanB(int nb) {     // <<<1,1>>>
    int run = 0;
    for (int b = 0; b < nb; b++) {
        int t = g_bsum[b];
        g_bsum[b] = run;
        run += t;
    }
}

__global__ void k_scanC(int N) {
    int i = blockIdx.x * blockDim.x + threadIdx.x;
    if (i < N) g_off[i + 1] += g_bsum[i >> 10];
    if (i == 0) g_off[0] = 0;
}

__global__ void k_cursor(int N) {
    int i = blockIdx.x * blockDim.x + threadIdx.x;
    if (i < N) g_cur[i] = g_off[i];
}

__global__ void k_scatter(const int* __restrict__ ei, int E_orig, int E_tot) {
    int i = blockIdx.x * blockDim.x + threadIdx.x;
    if (i >= E_tot) return;
    int src, dst;
    if (i < E_orig) { src = ei[i]; dst = ei[E_orig + i]; }
    else            { src = i - E_orig; dst = src; }
    int p = atomicAdd(&g_cur[dst], 1);
    g_csr[p] = src;
}

// ---------------- GEMM1: h1 = x @ W1  (+ e1_src/e1_dst) ----------------
// tile: 128 nodes x 64 cols, K-chunks of 32. Thread: 4 nodes x 8 cols (one head).
__global__ __launch_bounds__(256) void k_gemm1(
    const float* __restrict__ x, const float* __restrict__ W1,
    const float* __restrict__ a1s, const float* __restrict__ a1d, int N)
{
    __shared__ float xs[128 * 33];   // [node][k], stride 33 -> conflict free reads
    __shared__ float ws[32 * 64];    // [k][col]
    int t  = threadIdx.x;
    int ng = t & 31;     // node lane (nodes ng, ng+32, ng+64, ng+96)
    int cg = t >> 5;     // head index 0..7 (cols cg*8 .. cg*8+7)
    int n0 = blockIdx.x * 128;

    float acc[4][8];
#pragma unroll
    for (int j = 0; j < 4; j++)
#pragma unroll
        for (int c = 0; c < 8; c++) acc[j][c] = 0.f;

    for (int k0 = 0; k0 < IN_CH; k0 += 32) {
        // load x tile: 128 rows x 32 k = 1024 float4, 4 per thread
#pragma unroll
        for (int r = 0; r < 4; r++) {
            int f4   = t + r * 256;
            int node = f4 >> 3;
            int kk4  = f4 & 7;
            int gn   = n0 + node;
            float4 v = make_float4(0.f, 0.f, 0.f, 0.f);
            if (gn < N)
                v = *reinterpret_cast<const float4*>(&x[(size_t)gn * IN_CH + k0 + kk4 * 4]);
            float* p = &xs[node * 33 + kk4 * 4];
            p[0] = v.x; p[1] = v.y; p[2] = v.z; p[3] = v.w;
        }
        // load W tile: 32 x 64 = 512 float4, 2 per thread
#pragma unroll
        for (int r = 0; r < 2; r++) {
            int f4 = t + r * 256;
            int kk = f4 >> 4;
            int c4 = f4 & 15;
            *reinterpret_cast<float4*>(&ws[kk * 64 + c4 * 4]) =
                *reinterpret_cast<const float4*>(&W1[(size_t)(k0 + kk) * H1F + c4 * 4]);
        }
        __syncthreads();
#pragma unroll
        for (int k = 0; k < 32; k++) {
            float xv[4];
#pragma unroll
            for (int j = 0; j < 4; j++) xv[j] = xs[(ng + 32 * j) * 33 + k];
            float4 w0 = *reinterpret_cast<const float4*>(&ws[k * 64 + cg * 8]);
            float4 w1 = *reinterpret_cast<const float4*>(&ws[k * 64 + cg * 8 + 4]);
            float wv[8] = {w0.x, w0.y, w0.z, w0.w, w1.x, w1.y, w1.z, w1.w};
#pragma unroll
            for (int j = 0; j < 4; j++)
#pragma unroll
                for (int c = 0; c < 8; c++)
                    acc[j][c] = fmaf(xv[j], wv[c], acc[j][c]);
        }
        __syncthreads();
    }

    float as[8], ad[8];
#pragma unroll
    for (int c = 0; c < 8; c++) { as[c] = a1s[cg * 8 + c]; ad[c] = a1d[cg * 8 + c]; }

#pragma unroll
    for (int j = 0; j < 4; j++) {
        int node = n0 + ng + 32 * j;
        if (node >= N) continue;
        float es = 0.f, ed = 0.f;
#pragma unroll
        for (int c = 0; c < 8; c++) {
            es = fmaf(acc[j][c], as[c], es);
            ed = fmaf(acc[j][c], ad[c], ed);
        }
        *reinterpret_cast<float4*>(&g_h1[(size_t)node * H1F + cg * 8]) =
            make_float4(acc[j][0], acc[j][1], acc[j][2], acc[j][3]);
        *reinterpret_cast<float4*>(&g_h1[(size_t)node * H1F + cg * 8 + 4]) =
            make_float4(acc[j][4], acc[j][5], acc[j][6], acc[j][7]);
        g_e1s[node * 8 + cg] = es;
        g_e1d[node * 8 + cg] = ed;
    }
}

// ---------------- layer-1 edge aggregation (warp per dst) ----------------
// No segment-max needed: logits are O(1), exp() is safe, and
// alpha = exp(l)/sum exp(l) is identical to the max-subtracted form.
__global__ void k_edge1(const float* __restrict__ b1, int N) {
    int w = (blockIdx.x * blockDim.x + threadIdx.x) >> 5;
    if (w >= N) return;
    int lane = threadIdx.x & 31;
    int h0 = lane >> 3;              // feature f0=lane -> head lane/8
    const float ed0 = g_e1d[w * 8 + h0];
    const float ed1 = g_e1d[w * 8 + 4 + h0];   // f1 = lane+32 -> head 4+lane/8
    int beg = g_off[w], end = g_off[w + 1];
    float acc0 = 0.f, acc1 = 0.f, dn0 = 0.f, dn1 = 0.f;
    for (int i = beg; i < end; i++) {
        int s = __ldg(&g_csr[i]);
        float t0 = __ldg(&g_e1s[s * 8 + h0]) + ed0;
        float t1 = __ldg(&g_e1s[s * 8 + 4 + h0]) + ed1;
        t0 = t0 > 0.f ? t0 : 0.2f * t0;
        t1 = t1 > 0.f ? t1 : 0.2f * t1;
        float w0 = __expf(t0);
        float w1 = __expf(t1);
        acc0 = fmaf(w0, __ldg(&g_h1[(size_t)s * H1F + lane]), acc0);
        acc1 = fmaf(w1, __ldg(&g_h1[(size_t)s * H1F + 32 + lane]), acc1);
        dn0 += w0; dn1 += w1;
    }
    float v0 = acc0 / dn0 + b1[lane];
    float v1 = acc1 / dn1 + b1[lane + 32];
    v0 = v0 > 0.f ? v0 : (__expf(v0) - 1.f);   // ELU
    v1 = v1 > 0.f ? v1 : (__expf(v1) - 1.f);
    g_hact[(size_t)w * H1F + lane]      = v0;
    g_hact[(size_t)w * H1F + 32 + lane] = v1;
}

// ---------------- GEMM2: h2 = hact @ W2 (+ e2_src/e2_dst) ----------------
__global__ __launch_bounds__(256) void k_gemm2(
    const float* __restrict__ W2, const float* __restrict__ a2s,
    const float* __restrict__ a2d, int N)
{
    __shared__ float hs[64 * 65];
    __shared__ float ws[64 * 16];
    __shared__ float h2s[64 * 17];
    int t  = threadIdx.x;
    int n0 = blockIdx.x * 64;
#pragma unroll
    for (int r = 0; r < 4; r++) {
        int f4   = t + r * 256;
        int node = f4 >> 4;
        int k4   = f4 & 15;
        int gn   = n0 + node;
        float4 v = make_float4(0.f, 0.f, 0.f, 0.f);
        if (gn < N)
            v = *reinterpret_cast<const float4*>(&g_hact[(size_t)gn * H1F + k4 * 4]);
        float* p = &hs[node * 65 + k4 * 4];
        p[0] = v.x; p[1] = v.y; p[2] = v.z; p[3] = v.w;
    }
    {   // W2: 64x16 = 256 float4
        int k  = t >> 2;
        int c4 = t & 3;
        *reinterpret_cast<float4*>(&ws[k * 16 + c4 * 4]) =
            *reinterpret_cast<const float4*>(&W2[k * 16 + c4 * 4]);
    }
    __syncthreads();

    int j  = t >> 2;          // node within tile
    int c0 = (t & 3) * 4;     // output col group
    float acc[4] = {0.f, 0.f, 0.f, 0.f};
#pragma unroll
    for (int k = 0; k < 64; k++) {
        float  xv = hs[j * 65 + k];
        float4 wv = *reinterpret_cast<const float4*>(&ws[k * 16 + c0]);
        acc[0] = fmaf(xv, wv.x, acc[0]);
        acc[1] = fmaf(xv, wv.y, acc[1]);
        acc[2] = fmaf(xv, wv.z, acc[2]);
        acc[3] = fmaf(xv, wv.w, acc[3]);
    }
    int gn = n0 + j;
    if (gn < N)
        *reinterpret_cast<float4*>(&g_h2[(size_t)gn * OUT_CH + c0]) =
            make_float4(acc[0], acc[1], acc[2], acc[3]);
#pragma unroll
    for (int c = 0; c < 4; c++) h2s[j * 17 + c0 + c] = acc[c];
    __syncthreads();
    if (t < 64) {
        int gn2 = n0 + t;
        if (gn2 < N) {
            float es = 0.f, ed = 0.f;
#pragma unroll
            for (int c = 0; c < OUT_CH; c++) {
                float v = h2s[t * 17 + c];
                es = fmaf(v, a2s[c], es);
                ed = fmaf(v, a2d[c], ed);
            }
            g_e2s[gn2] = es;
            g_e2d[gn2] = ed;
        }
    }
}

// ---------------- layer-2 edge aggregation + fused log_softmax ----------------
__global__ void k_edge2(const float* __restrict__ b2, float* __restrict__ out, int N) {
    int w = (blockIdx.x * blockDim.x + threadIdx.x) >> 5;
    if (w >= N) return;
    int lane = threadIdx.x & 31;
    int c = lane & 15;
    int g = lane >> 4;        // two edges per iteration (half-warp each)
    float ed = g_e2d[w];
    int beg = g_off[w], end = g_off[w + 1];
    float acc = 0.f, dn = 0.f;
    for (int i = beg + g; i < end; i += 2) {
        int s = __ldg(&g_csr[i]);
        float t = __ldg(&g_e2s[s]) + ed;
        t = t > 0.f ? t : 0.2f * t;
        float wt = __expf(t);
        acc = fmaf(wt, __ldg(&g_h2[(size_t)s * OUT_CH + c]), acc);
        dn += wt;
    }
    acc += __shfl_xor_sync(0xffffffffu, acc, 16);
    dn  += __shfl_xor_sync(0xffffffffu, dn, 16);
    float v = acc / dn + b2[c];
    // log_softmax over the 16 channels (both half-warps hold identical copies)
    float m = v;
#pragma unroll
    for (int o = 8; o; o >>= 1) m = fmaxf(m, __shfl_xor_sync(0xffffffffu, m, o));
    float S = __expf(v - m);
#pragma unroll
    for (int o = 8; o; o >>= 1) S += __shfl_xor_sync(0xffffffffu, S, o);
    if (lane < 16) out[(size_t)w * OUT_CH + c] = (v - m) - __logf(S);
}

// ---------------- launch ----------------
extern "C" void kernel_launch(void* const* d_in, const int* in_sizes, int n_in,
                              void* d_out, int out_size)
{
    const float* x   = (const float*)d_in[0];
    const int*   ei  = (const int*)  d_in[1];
    const float* W1  = (const float*)d_in[2];
    const float* a1s = (const float*)d_in[3];
    const float* a1d = (const float*)d_in[4];
    const float* b1  = (const float*)d_in[5];
    const float* W2  = (const float*)d_in[6];
    const float* a2s = (const float*)d_in[7];
    const float* a2d = (const float*)d_in[8];
    const float* b2  = (const float*)d_in[9];
    float* out = (float*)d_out;

    int N      = in_sizes[0] / IN_CH;     // 100000
    int E_orig = in_sizes[1] / 2;         // 3200000
    int E_tot  = E_orig + N;

    // CSR build (shared by both layers)
    k_zero   <<<(N + 255) / 256, 256>>>(N);
    k_deg    <<<(E_tot + 255) / 256, 256>>>(ei, E_orig, E_tot);
    k_scanA  <<<(N + 1023) / 1024, 1024>>>(N);
    k_scanB  <<<1, 1>>>((N + 1023) / 1024);
    k_scanC  <<<(N + 255) / 256, 256>>>(N);
    k_cursor <<<(N + 255) / 256, 256>>>(N);
    k_scatter<<<(E_tot + 255) / 256, 256>>>(ei, E_orig, E_tot);

    // layer 1
    k_gemm1<<<(N + 127) / 128, 256>>>(x, W1, a1s, a1d, N);
    k_edge1<<<(N * 32 + 255) / 256, 256>>>(b1, N);

    // layer 2 + fused log_softmax
    k_gemm2<<<(N + 63) / 64, 256>>>(W2, a2s, a2d, N);
    k_edge2<<<(N * 32 + 255) / 256, 256>>>(b2, out, N);
}

// round 5
// speedup vs baseline: 1.0451x; 1.0451x over previous
#include <cuda_runtime.h>
#include <cuda_bf16.h>
#include <math.h>
#include <stdint.h>

#define N_MAX   100000
#define E_MAX   3300000
#define IN_CH   512
#define H1F     64      // heads1*ch1
#define OUT_CH  16

// ---------------- device scratch (no allocation allowed) ----------------
__device__ float g_h1  [(size_t)N_MAX * H1F];    // x@W1
__device__ float g_e1s [(size_t)N_MAX * 8];
__device__ float g_e1d [(size_t)N_MAX * 8];
__device__ float g_hact[(size_t)N_MAX * H1F];    // elu(layer1 out)
__device__ float g_h2  [(size_t)N_MAX * OUT_CH]; // hact@W2
__device__ float g_e2s [N_MAX];
__device__ float g_e2d [N_MAX];
__device__ int   g_deg [N_MAX];
__device__ int   g_off [N_MAX + 1];
__device__ int   g_cur [N_MAX];
__device__ int   g_csr [E_MAX];
__device__ int   g_bsum[128];

// ---------------- packed f32x2 helpers (base sm_100 feature, no 'a' needed) ----
__device__ __forceinline__ void fma_f32x2(unsigned long long& acc,
                                          unsigned long long a, unsigned long long b) {
    asm("fma.rn.f32x2 %0, %1, %2, %0;" : "+l"(acc) : "l"(a), "l"(b));
}
__device__ __forceinline__ unsigned long long pack_ff(float v) {
    unsigned long long r;
    asm("mov.b64 %0, {%1, %1};" : "=l"(r) : "f"(v));
    return r;
}
__device__ __forceinline__ void unpack_ff(unsigned long long p, float& lo, float& hi) {
    asm("mov.b64 {%0, %1}, %2;" : "=f"(lo), "=f"(hi) : "l"(p));
}

// ---------------- CSR build ----------------
__global__ void k_zero(int N) {
    int i = blockIdx.x * blockDim.x + threadIdx.x;
    if (i < N) g_deg[i] = 0;
}

__global__ void k_deg(const int* __restrict__ ei, int E_orig, int E_tot) {
    int i = blockIdx.x * blockDim.x + threadIdx.x;
    if (i >= E_tot) return;
    int dst = (i < E_orig) ? ei[E_orig + i] : (i - E_orig);
    atomicAdd(&g_deg[dst], 1);
}

__global__ void k_scanA(int N) {      // grid: ceil(N/1024), block 1024
    __shared__ int s[1024];
    int tid = threadIdx.x;
    int i = blockIdx.x * 1024 + tid;
    int v = (i < N) ? g_deg[i] : 0;
    s[tid] = v;
    __syncthreads();
    for (int o = 1; o < 1024; o <<= 1) {
        int t = (tid >= o) ? s[tid - o] : 0;
        __syncthreads();
        s[tid] += t;
        __syncthreads();
    }
    if (i < N) g_off[i + 1] = s[tid];
    if (tid == 1023) g_bsum[blockIdx.x] = s[1023];
}

__global__ void k_scanB(int nb) {     // <<<1,1>>>
    int run = 0;
    for (int b = 0; b < nb; b++) {
        int t = g_bsum[b];
        g_bsum[b] = run;
        run += t;
    }
}

__global__ void k_scanC(int N) {
    int i = blockIdx.x * blockDim.x + threadIdx.x;
    if (i < N) g_off[i + 1] += g_bsum[i >> 10];
    if (i == 0) g_off[0] = 0;
}

__global__ void k_cursor(int N) {
    int i = blockIdx.x * blockDim.x + threadIdx.x;
    if (i < N) g_cur[i] = g_off[i];
}

__global__ void k_scatter(const int* __restrict__ ei, int E_orig, int E_tot) {
    int i = blockIdx.x * blockDim.x + threadIdx.x;
    if (i >= E_tot) return;
    int src, dst;
    if (i < E_orig) { src = ei[i]; dst = ei[E_orig + i]; }
    else            { src = i - E_orig; dst = src; }
    int p = atomicAdd(&g_cur[dst], 1);
    g_csr[p] = src;
}

// ---------------- GEMM1: h1 = x @ W1  (+ e1_src/e1_dst), packed f32x2 ----------
// tile: 128 nodes x 64 cols, K-chunks of 32. Thread: 4 nodes x 8 cols (one head).
// Accumulators packed over column pairs: acc2[j][c2] = {col 2*c2, col 2*c2+1}.
__global__ __launch_bounds__(256) void k_gemm1(
    const float* __restrict__ x, const float* __restrict__ W1,
    const float* __restrict__ a1s, const float* __restrict__ a1d, int N)
{
    __shared__ float xs[128 * 33];   // [node][k], stride 33 -> conflict free reads
    __shared__ float ws[32 * 64];    // [k][col]
    int t  = threadIdx.x;
    int ng = t & 31;     // node lane (nodes ng, ng+32, ng+64, ng+96)
    int cg = t >> 5;     // head index 0..7 (cols cg*8 .. cg*8+7)
    int n0 = blockIdx.x * 128;

    unsigned long long acc2[4][4];
#pragma unroll
    for (int j = 0; j < 4; j++)
#pragma unroll
        for (int c = 0; c < 4; c++) acc2[j][c] = 0ULL;   // {0.f, 0.f}

    for (int k0 = 0; k0 < IN_CH; k0 += 32) {
        // load x tile: 128 rows x 32 k = 1024 float4, 4 per thread
#pragma unroll
        for (int r = 0; r < 4; r++) {
            int f4   = t + r * 256;
            int node = f4 >> 3;
            int kk4  = f4 & 7;
            int gn   = n0 + node;
            float4 v = make_float4(0.f, 0.f, 0.f, 0.f);
            if (gn < N)
                v = *reinterpret_cast<const float4*>(&x[(size_t)gn * IN_CH + k0 + kk4 * 4]);
            float* p = &xs[node * 33 + kk4 * 4];
            p[0] = v.x; p[1] = v.y; p[2] = v.z; p[3] = v.w;
        }
        // load W tile: 32 x 64 = 512 float4, 2 per thread
#pragma unroll
        for (int r = 0; r < 2; r++) {
            int f4 = t + r * 256;
            int kk = f4 >> 4;
            int c4 = f4 & 15;
            *reinterpret_cast<float4*>(&ws[kk * 64 + c4 * 4]) =
                *reinterpret_cast<const float4*>(&W1[(size_t)(k0 + kk) * H1F + c4 * 4]);
        }
        __syncthreads();
#pragma unroll
        for (int k = 0; k < 32; k++) {
            // two 16B vector loads = 4 packed {c,c+1} operand pairs
            ulonglong2 w01 = *reinterpret_cast<const ulonglong2*>(&ws[k * 64 + cg * 8]);
            ulonglong2 w23 = *reinterpret_cast<const ulonglong2*>(&ws[k * 64 + cg * 8 + 4]);
#pragma unroll
            for (int j = 0; j < 4; j++) {
                unsigned long long xp = pack_ff(xs[(ng + 32 * j) * 33 + k]);
                fma_f32x2(acc2[j][0], xp, w01.x);
                fma_f32x2(acc2[j][1], xp, w01.y);
                fma_f32x2(acc2[j][2], xp, w23.x);
                fma_f32x2(acc2[j][3], xp, w23.y);
            }
        }
        __syncthreads();
    }

    float as[8], ad[8];
#pragma unroll
    for (int c = 0; c < 8; c++) { as[c] = a1s[cg * 8 + c]; ad[c] = a1d[cg * 8 + c]; }

#pragma unroll
    for (int j = 0; j < 4; j++) {
        int node = n0 + ng + 32 * j;
        if (node >= N) continue;
        float acc[8];
#pragma unroll
        for (int c = 0; c < 4; c++) unpack_ff(acc2[j][c], acc[2 * c], acc[2 * c + 1]);
        float es = 0.f, ed = 0.f;
#pragma unroll
        for (int c = 0; c < 8; c++) {
            es = fmaf(acc[c], as[c], es);
            ed = fmaf(acc[c], ad[c], ed);
        }
        *reinterpret_cast<float4*>(&g_h1[(size_t)node * H1F + cg * 8]) =
            make_float4(acc[0], acc[1], acc[2], acc[3]);
        *reinterpret_cast<float4*>(&g_h1[(size_t)node * H1F + cg * 8 + 4]) =
            make_float4(acc[4], acc[5], acc[6], acc[7]);
        g_e1s[node * 8 + cg] = es;
        g_e1d[node * 8 + cg] = ed;
    }
}

// ---------------- layer-1 edge aggregation (warp per dst) ----------------
// No segment-max needed: logits are O(1), exp() is safe, and
// alpha = exp(l)/sum exp(l) is identical to the max-subtracted form.
__global__ void k_edge1(const float* __restrict__ b1, int N) {
    int w = (blockIdx.x * blockDim.x + threadIdx.x) >> 5;
    if (w >= N) return;
    int lane = threadIdx.x & 31;
    int h0 = lane >> 3;              // feature f0=lane -> head lane/8
    const float ed0 = g_e1d[w * 8 + h0];
    const float ed1 = g_e1d[w * 8 + 4 + h0];   // f1 = lane+32 -> head 4+lane/8
    int beg = g_off[w], end = g_off[w + 1];
    float acc0 = 0.f, acc1 = 0.f, dn0 = 0.f, dn1 = 0.f;
    for (int i = beg; i < end; i++) {
        int s = __ldg(&g_csr[i]);
        float t0 = __ldg(&g_e1s[s * 8 + h0]) + ed0;
        float t1 = __ldg(&g_e1s[s * 8 + 4 + h0]) + ed1;
        t0 = t0 > 0.f ? t0 : 0.2f * t0;
        t1 = t1 > 0.f ? t1 : 0.2f * t1;
        float w0 = __expf(t0);
        float w1 = __expf(t1);
        acc0 = fmaf(w0, __ldg(&g_h1[(size_t)s * H1F + lane]), acc0);
        acc1 = fmaf(w1, __ldg(&g_h1[(size_t)s * H1F + 32 + lane]), acc1);
        dn0 += w0; dn1 += w1;
    }
    float v0 = acc0 / dn0 + b1[lane];
    float v1 = acc1 / dn1 + b1[lane + 32];
    v0 = v0 > 0.f ? v0 : (__expf(v0) - 1.f);   // ELU
    v1 = v1 > 0.f ? v1 : (__expf(v1) - 1.f);
    g_hact[(size_t)w * H1F + lane]      = v0;
    g_hact[(size_t)w * H1F + 32 + lane] = v1;
}

// ---------------- GEMM2: h2 = hact @ W2 (+ e2_src/e2_dst), packed f32x2 -------
__global__ __launch_bounds__(256) void k_gemm2(
    const float* __restrict__ W2, const float* __restrict__ a2s,
    const float* __restrict__ a2d, int N)
{
    __shared__ float hs[64 * 65];
    __shared__ float ws[64 * 16];
    __shared__ float h2s[64 * 17];
    int t  = threadIdx.x;
    int n0 = blockIdx.x * 64;
#pragma unroll
    for (int r = 0; r < 4; r++) {
        int f4   = t + r * 256;
        int node = f4 >> 4;
        int k4   = f4 & 15;
        int gn   = n0 + node;
        float4 v = make_float4(0.f, 0.f, 0.f, 0.f);
        if (gn < N)
            v = *reinterpret_cast<const float4*>(&g_hact[(size_t)gn * H1F + k4 * 4]);
        float* p = &hs[node * 65 + k4 * 4];
        p[0] = v.x; p[1] = v.y; p[2] = v.z; p[3] = v.w;
    }
    {   // W2: 64x16 = 256 float4
        int k  = t >> 2;
        int c4 = t & 3;
        *reinterpret_cast<float4*>(&ws[k * 16 + c4 * 4]) =
            *reinterpret_cast<const float4*>(&W2[k * 16 + c4 * 4]);
    }
    __syncthreads();

    int j  = t >> 2;          // node within tile
    int c0 = (t & 3) * 4;     // output col group
    unsigned long long acc2[2] = {0ULL, 0ULL};
#pragma unroll
    for (int k = 0; k < 64; k++) {
        unsigned long long xp = pack_ff(hs[j * 65 + k]);
        ulonglong2 wv = *reinterpret_cast<const ulonglong2*>(&ws[k * 16 + c0]);
        fma_f32x2(acc2[0], xp, wv.x);
        fma_f32x2(acc2[1], xp, wv.y);
    }
    float acc[4];
    unpack_ff(acc2[0], acc[0], acc[1]);
    unpack_ff(acc2[1], acc[2], acc[3]);
    int gn = n0 + j;
    if (gn < N)
        *reinterpret_cast<float4*>(&g_h2[(size_t)gn * OUT_CH + c0]) =
            make_float4(acc[0], acc[1], acc[2], acc[3]);
#pragma unroll
    for (int c = 0; c < 4; c++) h2s[j * 17 + c0 + c] = acc[c];
    __syncthreads();
    if (t < 64) {
        int gn2 = n0 + t;
        if (gn2 < N) {
            float es = 0.f, ed = 0.f;
#pragma unroll
            for (int c = 0; c < OUT_CH; c++) {
                float v = h2s[t * 17 + c];
                es = fmaf(v, a2s[c], es);
                ed = fmaf(v, a2d[c], ed);
            }
            g_e2s[gn2] = es;
            g_e2d[gn2] = ed;
        }
    }
}

// ---------------- layer-2 edge aggregation + fused log_softmax ----------------
__global__ void k_edge2(const float* __restrict__ b2, float* __restrict__ out, int N) {
    int w = (blockIdx.x * blockDim.x + threadIdx.x) >> 5;
    if (w >= N) return;
    int lane = threadIdx.x & 31;
    int c = lane & 15;
    int g = lane >> 4;        // two edges per iteration (half-warp each)
    float ed = g_e2d[w];
    int beg = g_off[w], end = g_off[w + 1];
    float acc = 0.f, dn = 0.f;
    for (int i = beg + g; i < end; i += 2) {
        int s = __ldg(&g_csr[i]);
        float t = __ldg(&g_e2s[s]) + ed;
        t = t > 0.f ? t : 0.2f * t;
        float wt = __expf(t);
        acc = fmaf(wt, __ldg(&g_h2[(size_t)s * OUT_CH + c]), acc);
        dn += wt;
    }
    acc += __shfl_xor_sync(0xffffffffu, acc, 16);
    dn  += __shfl_xor_sync(0xffffffffu, dn, 16);
    float v = acc / dn + b2[c];
    // log_softmax over the 16 channels (both half-warps hold identical copies)
    float m = v;
#pragma unroll
    for (int o = 8; o; o >>= 1) m = fmaxf(m, __shfl_xor_sync(0xffffffffu, m, o));
    float S = __expf(v - m);
#pragma unroll
    for (int o = 8; o; o >>= 1) S += __shfl_xor_sync(0xffffffffu, S, o);
    if (lane < 16) out[(size_t)w * OUT_CH + c] = (v - m) - __logf(S);
}

// ---------------- launch ----------------
extern "C" void kernel_launch(void* const* d_in, const int* in_sizes, int n_in,
                              void* d_out, int out_size)
{
    const float* x   = (const float*)d_in[0];
    const int*   ei  = (const int*)  d_in[1];
    const float* W1  = (const float*)d_in[2];
    const float* a1s = (const float*)d_in[3];
    const float* a1d = (const float*)d_in[4];
    const float* b1  = (const float*)d_in[5];
    const float* W2  = (const float*)d_in[6];
    const float* a2s = (const float*)d_in[7];
    const float* a2d = (const float*)d_in[8];
    const float* b2  = (const float*)d_in[9];
    float* out = (float*)d_out;

    int N      = in_sizes[0] / IN_CH;     // 100000
    int E_orig = in_sizes[1] / 2;         // 3200000
    int E_tot  = E_orig + N;

    // CSR build interleaved with gemm1 (independent); gemm1 placed at launch
    // index 3 so the fixed ncu skip-count lands on it next profile.
    k_zero   <<<(N + 255) / 256, 256>>>(N);
    k_deg    <<<(E_tot + 255) / 256, 256>>>(ei, E_orig, E_tot);
    k_scanA  <<<(N + 1023) / 1024, 1024>>>(N);
    k_gemm1  <<<(N + 127) / 128, 256>>>(x, W1, a1s, a1d, N);
    k_scanB  <<<1, 1>>>((N + 1023) / 1024);
    k_scanC  <<<(N + 255) / 256, 256>>>(N);
    k_cursor <<<(N + 255) / 256, 256>>>(N);
    k_scatter<<<(E_tot + 255) / 256, 256>>>(ei, E_orig, E_tot);

    // layer 1 aggregation
    k_edge1<<<(N * 32 + 255) / 256, 256>>>(b1, N);

    // layer 2 + fused log_softmax
    k_gemm2<<<(N + 63) / 64, 256>>>(W2, a2s, a2d, N);
    k_edge2<<<(N * 32 + 255) / 256, 256>>>(b2, out, N);
}

// round 6
// speedup vs baseline: 1.0707x; 1.0245x over previous
#include <cuda_runtime.h>
#include <cuda_bf16.h>
#include <math.h>
#include <stdint.h>

#define N_MAX   100000
#define E_MAX   3300000
#define IN_CH   512
#define H1F     64      // heads1*ch1
#define OUT_CH  16

// ---------------- device scratch (no allocation allowed) ----------------
__device__ float g_h1  [(size_t)N_MAX * H1F];    // x@W1
__device__ float g_e1s [(size_t)N_MAX * 8];
__device__ float g_e1d [(size_t)N_MAX * 8];
__device__ float g_hact[(size_t)N_MAX * H1F];    // elu(layer1 out)
__device__ float g_h2  [(size_t)N_MAX * OUT_CH]; // hact@W2
__device__ float g_e2s [N_MAX];
__device__ float g_e2d [N_MAX];
__device__ int   g_deg [N_MAX];
__device__ int   g_off [N_MAX + 1];
__device__ int   g_cur [N_MAX];
__device__ int   g_csr [E_MAX];
__device__ int   g_bsum[128];

// ---------------- packed f32x2 helpers (base sm_100 feature) ----------------
__device__ __forceinline__ void fma_f32x2(unsigned long long& acc,
                                          unsigned long long a, unsigned long long b) {
    asm("fma.rn.f32x2 %0, %1, %2, %0;" : "+l"(acc) : "l"(a), "l"(b));
}
__device__ __forceinline__ unsigned long long pack_ff(float v) {
    unsigned long long r;
    asm("mov.b64 %0, {%1, %1};" : "=l"(r) : "f"(v));
    return r;
}
__device__ __forceinline__ void unpack_ff(unsigned long long p, float& lo, float& hi) {
    asm("mov.b64 {%0, %1}, %2;" : "=f"(lo), "=f"(hi) : "l"(p));
}

// ---------------- CSR build ----------------
__global__ void k_zero(int N) {
    int i = blockIdx.x * blockDim.x + threadIdx.x;
    if (i < N) g_deg[i] = 0;
}

__global__ void k_deg(const int* __restrict__ ei, int E_orig, int E_tot) {
    int i = blockIdx.x * blockDim.x + threadIdx.x;
    if (i >= E_tot) return;
    int dst = (i < E_orig) ? ei[E_orig + i] : (i - E_orig);
    atomicAdd(&g_deg[dst], 1);
}

__global__ void k_scanA(int N) {      // grid: ceil(N/1024), block 1024
    __shared__ int s[1024];
    int tid = threadIdx.x;
    int i = blockIdx.x * 1024 + tid;
    int v = (i < N) ? g_deg[i] : 0;
    s[tid] = v;
    __syncthreads();
    for (int o = 1; o < 1024; o <<= 1) {
        int t = (tid >= o) ? s[tid - o] : 0;
        __syncthreads();
        s[tid] += t;
        __syncthreads();
    }
    if (i < N) g_off[i + 1] = s[tid];
    if (tid == 1023) g_bsum[blockIdx.x] = s[1023];
}

__global__ void k_scanB(int nb) {     // <<<1,1>>>
    int run = 0;
    for (int b = 0; b < nb; b++) {
        int t = g_bsum[b];
        g_bsum[b] = run;
        run += t;
    }
}

__global__ void k_scanC(int N) {
    int i = blockIdx.x * blockDim.x + threadIdx.x;
    if (i < N) g_off[i + 1] += g_bsum[i >> 10];
    if (i == 0) g_off[0] = 0;
}

__global__ void k_cursor(int N) {
    int i = blockIdx.x * blockDim.x + threadIdx.x;
    if (i < N) g_cur[i] = g_off[i];
}

__global__ void k_scatter(const int* __restrict__ ei, int E_orig, int E_tot) {
    int i = blockIdx.x * blockDim.x + threadIdx.x;
    if (i >= E_tot) return;
    int src, dst;
    if (i < E_orig) { src = ei[i]; dst = ei[E_orig + i]; }
    else            { src = i - E_orig; dst = src; }
    int p = atomicAdd(&g_cur[dst], 1);
    g_csr[p] = src;
}

// ---------------- GEMM1: h1 = x @ W1  (+ e1_src/e1_dst) ----------------
// tile: 128 nodes x 64 cols, K-chunks of 32. Thread: 4 nodes x 8 cols.
// Register-staged prefetch of the next x chunk hides LDG latency inside the
// compute phase (W1 is L1/L2-hot: 128KB reused by all CTAs, no staging needed).
__global__ __launch_bounds__(256, 3) void k_gemm1(
    const float* __restrict__ x, const float* __restrict__ W1,
    const float* __restrict__ a1s, const float* __restrict__ a1d, int N)
{
    __shared__ float xs[128 * 33];   // [node][k], stride 33 -> conflict free
    __shared__ float ws[32 * 64];    // [k][col]
    int t  = threadIdx.x;
    int ng = t & 31;     // node lane (nodes ng, ng+32, ng+64, ng+96)
    int cg = t >> 5;     // head index 0..7 (cols cg*8 .. cg*8+7)
    int n0 = blockIdx.x * 128;

    // per-thread x-stage geometry (fixed across chunks)
    const int st_node = t >> 1;           // 0..127 (two threads per row, 2 float4 each... )
    // Layout: 1024 float4s per chunk; thread r-th piece: f4 = t + r*256
    // piece r: node=(t+r*256)>>3, kk4=(t+r*256)&7
    float4 xstg[4];
    const float* xrow[4];
    float* xdst[4];
    bool  xok[4];
#pragma unroll
    for (int r = 0; r < 4; r++) {
        int f4   = t + r * 256;
        int node = f4 >> 3;
        int kk4  = f4 & 7;
        int gn   = n0 + node;
        xok[r]  = (gn < N);
        xrow[r] = &x[(size_t)(xok[r] ? gn : 0) * IN_CH + kk4 * 4];
        xdst[r] = &xs[node * 33 + kk4 * 4];
    }
    (void)st_node;

    unsigned long long acc2[4][4];
#pragma unroll
    for (int j = 0; j < 4; j++)
#pragma unroll
        for (int c = 0; c < 4; c++) acc2[j][c] = 0ULL;

    // ---- prologue: load chunk 0 (x + w) and store to smem
#pragma unroll
    for (int r = 0; r < 4; r++) {
        float4 v = make_float4(0.f, 0.f, 0.f, 0.f);
        if (xok[r]) v = *reinterpret_cast<const float4*>(xrow[r]);
        xstg[r] = v;
    }
#pragma unroll
    for (int r = 0; r < 2; r++) {
        int f4 = t + r * 256;
        int kk = f4 >> 4;
        int c4 = f4 & 15;
        *reinterpret_cast<float4*>(&ws[kk * 64 + c4 * 4]) =
            *reinterpret_cast<const float4*>(&W1[(size_t)kk * H1F + c4 * 4]);
    }
#pragma unroll
    for (int r = 0; r < 4; r++) {
        float* p = xdst[r];
        p[0] = xstg[r].x; p[1] = xstg[r].y; p[2] = xstg[r].z; p[3] = xstg[r].w;
    }
    __syncthreads();

    for (int ch = 0; ch < 16; ch++) {
        // prefetch next chunk's x into registers (latency overlapped with compute)
        if (ch < 15) {
            int k0n = (ch + 1) * 32;
#pragma unroll
            for (int r = 0; r < 4; r++) {
                float4 v = make_float4(0.f, 0.f, 0.f, 0.f);
                if (xok[r]) v = *reinterpret_cast<const float4*>(xrow[r] + k0n);
                xstg[r] = v;
            }
        }
        // compute current chunk
#pragma unroll
        for (int k = 0; k < 32; k++) {
            ulonglong2 w01 = *reinterpret_cast<const ulonglong2*>(&ws[k * 64 + cg * 8]);
            ulonglong2 w23 = *reinterpret_cast<const ulonglong2*>(&ws[k * 64 + cg * 8 + 4]);
#pragma unroll
            for (int j = 0; j < 4; j++) {
                unsigned long long xp = pack_ff(xs[(ng + 32 * j) * 33 + k]);
                fma_f32x2(acc2[j][0], xp, w01.x);
                fma_f32x2(acc2[j][1], xp, w01.y);
                fma_f32x2(acc2[j][2], xp, w23.x);
                fma_f32x2(acc2[j][3], xp, w23.y);
            }
        }
        __syncthreads();
        if (ch < 15) {
            int k0n = (ch + 1) * 32;
            // w tile for next chunk (hot in L1/L2)
#pragma unroll
            for (int r = 0; r < 2; r++) {
                int f4 = t + r * 256;
                int kk = f4 >> 4;
                int c4 = f4 & 15;
                *reinterpret_cast<float4*>(&ws[kk * 64 + c4 * 4]) =
                    *reinterpret_cast<const float4*>(&W1[(size_t)(k0n + kk) * H1F + c4 * 4]);
            }
#pragma unroll
            for (int r = 0; r < 4; r++) {
                float* p = xdst[r];
                p[0] = xstg[r].x; p[1] = xstg[r].y; p[2] = xstg[r].z; p[3] = xstg[r].w;
            }
            __syncthreads();
        }
    }

    float as[8], ad[8];
#pragma unroll
    for (int c = 0; c < 8; c++) { as[c] = a1s[cg * 8 + c]; ad[c] = a1d[cg * 8 + c]; }

#pragma unroll
    for (int j = 0; j < 4; j++) {
        int node = n0 + ng + 32 * j;
        if (node >= N) continue;
        float acc[8];
#pragma unroll
        for (int c = 0; c < 4; c++) unpack_ff(acc2[j][c], acc[2 * c], acc[2 * c + 1]);
        float es = 0.f, ed = 0.f;
#pragma unroll
        for (int c = 0; c < 8; c++) {
            es = fmaf(acc[c], as[c], es);
            ed = fmaf(acc[c], ad[c], ed);
        }
        *reinterpret_cast<float4*>(&g_h1[(size_t)node * H1F + cg * 8]) =
            make_float4(acc[0], acc[1], acc[2], acc[3]);
        *reinterpret_cast<float4*>(&g_h1[(size_t)node * H1F + cg * 8 + 4]) =
            make_float4(acc[4], acc[5], acc[6], acc[7]);
        g_e1s[node * 8 + cg] = es;
        g_e1d[node * 8 + cg] = ed;
    }
}

// ---------------- layer-1 edge aggregation (warp per dst, unroll x2) ----------
// No segment-max needed: logits are O(1), exp() is safe, and
// alpha = exp(l)/sum exp(l) is identical to the max-subtracted form.
__global__ void k_edge1(const float* __restrict__ b1, int N) {
    int w = (blockIdx.x * blockDim.x + threadIdx.x) >> 5;
    if (w >= N) return;
    int lane = threadIdx.x & 31;
    int h0 = lane >> 3;              // feature f0=lane -> head lane/8
    const float ed0 = g_e1d[w * 8 + h0];
    const float ed1 = g_e1d[w * 8 + 4 + h0];   // f1 = lane+32 -> head 4+lane/8
    int beg = g_off[w], end = g_off[w + 1];
    float acc0 = 0.f, acc1 = 0.f, dn0 = 0.f, dn1 = 0.f;
    int i = beg;
    for (; i + 2 <= end; i += 2) {
        int sA = __ldg(&g_csr[i]);
        int sB = __ldg(&g_csr[i + 1]);
        float tA0 = __ldg(&g_e1s[sA * 8 + h0]) + ed0;
        float tA1 = __ldg(&g_e1s[sA * 8 + 4 + h0]) + ed1;
        float tB0 = __ldg(&g_e1s[sB * 8 + h0]) + ed0;
        float tB1 = __ldg(&g_e1s[sB * 8 + 4 + h0]) + ed1;
        float hA0 = __ldg(&g_h1[(size_t)sA * H1F + lane]);
        float hA1 = __ldg(&g_h1[(size_t)sA * H1F + 32 + lane]);
        float hB0 = __ldg(&g_h1[(size_t)sB * H1F + lane]);
        float hB1 = __ldg(&g_h1[(size_t)sB * H1F + 32 + lane]);
        tA0 = tA0 > 0.f ? tA0 : 0.2f * tA0;
        tA1 = tA1 > 0.f ? tA1 : 0.2f * tA1;
        tB0 = tB0 > 0.f ? tB0 : 0.2f * tB0;
        tB1 = tB1 > 0.f ? tB1 : 0.2f * tB1;
        float wA0 = __expf(tA0), wA1 = __expf(tA1);
        float wB0 = __expf(tB0), wB1 = __expf(tB1);
        acc0 = fmaf(wA0, hA0, acc0); dn0 += wA0;
        acc1 = fmaf(wA1, hA1, acc1); dn1 += wA1;
        acc0 = fmaf(wB0, hB0, acc0); dn0 += wB0;
        acc1 = fmaf(wB1, hB1, acc1); dn1 += wB1;
    }
    if (i < end) {
        int s = __ldg(&g_csr[i]);
        float t0 = __ldg(&g_e1s[s * 8 + h0]) + ed0;
        float t1 = __ldg(&g_e1s[s * 8 + 4 + h0]) + ed1;
        t0 = t0 > 0.f ? t0 : 0.2f * t0;
        t1 = t1 > 0.f ? t1 : 0.2f * t1;
        float w0 = __expf(t0);
        float w1 = __expf(t1);
        acc0 = fmaf(w0, __ldg(&g_h1[(size_t)s * H1F + lane]), acc0);
        acc1 = fmaf(w1, __ldg(&g_h1[(size_t)s * H1F + 32 + lane]), acc1);
        dn0 += w0; dn1 += w1;
    }
    float v0 = acc0 / dn0 + b1[lane];
    float v1 = acc1 / dn1 + b1[lane + 32];
    v0 = v0 > 0.f ? v0 : (__expf(v0) - 1.f);   // ELU
    v1 = v1 > 0.f ? v1 : (__expf(v1) - 1.f);
    g_hact[(size_t)w * H1F + lane]      = v0;
    g_hact[(size_t)w * H1F + 32 + lane] = v1;
}

// ---------------- GEMM2: h2 = hact @ W2 (+ e2_src/e2_dst), packed f32x2 -------
__global__ __launch_bounds__(256) void k_gemm2(
    const float* __restrict__ W2, const float* __restrict__ a2s,
    const float* __restrict__ a2d, int N)
{
    __shared__ float hs[64 * 65];
    __shared__ float ws[64 * 16];
    __shared__ float h2s[64 * 17];
    int t  = threadIdx.x;
    int n0 = blockIdx.x * 64;
#pragma unroll
    for (int r = 0; r < 4; r++) {
        int f4   = t + r * 256;
        int node = f4 >> 4;
        int k4   = f4 & 15;
        int gn   = n0 + node;
        float4 v = make_float4(0.f, 0.f, 0.f, 0.f);
        if (gn < N)
            v = *reinterpret_cast<const float4*>(&g_hact[(size_t)gn * H1F + k4 * 4]);
        float* p = &hs[node * 65 + k4 * 4];
        p[0] = v.x; p[1] = v.y; p[2] = v.z; p[3] = v.w;
    }
    {   // W2: 64x16 = 256 float4
        int k  = t >> 2;
        int c4 = t & 3;
        *reinterpret_cast<float4*>(&ws[k * 16 + c4 * 4]) =
            *reinterpret_cast<const float4*>(&W2[k * 16 + c4 * 4]);
    }
    __syncthreads();

    int j  = t >> 2;          // node within tile
    int c0 = (t & 3) * 4;     // output col group
    unsigned long long acc2[2] = {0ULL, 0ULL};
#pragma unroll
    for (int k = 0; k < 64; k++) {
        unsigned long long xp = pack_ff(hs[j * 65 + k]);
        ulonglong2 wv = *reinterpret_cast<const ulonglong2*>(&ws[k * 16 + c0]);
        fma_f32x2(acc2[0], xp, wv.x);
        fma_f32x2(acc2[1], xp, wv.y);
    }
    float acc[4];
    unpack_ff(acc2[0], acc[0], acc[1]);
    unpack_ff(acc2[1], acc[2], acc[3]);
    int gn = n0 + j;
    if (gn < N)
        *reinterpret_cast<float4*>(&g_h2[(size_t)gn * OUT_CH + c0]) =
            make_float4(acc[0], acc[1], acc[2], acc[3]);
#pragma unroll
    for (int c = 0; c < 4; c++) h2s[j * 17 + c0 + c] = acc[c];
    __syncthreads();
    if (t < 64) {
        int gn2 = n0 + t;
        if (gn2 < N) {
            float es = 0.f, ed = 0.f;
#pragma unroll
            for (int c = 0; c < OUT_CH; c++) {
                float v = h2s[t * 17 + c];
                es = fmaf(v, a2s[c], es);
                ed = fmaf(v, a2d[c], ed);
            }
            g_e2s[gn2] = es;
            g_e2d[gn2] = ed;
        }
    }
}

// ---------------- layer-2 edge aggregation + fused log_softmax ----------------
__global__ void k_edge2(const float* __restrict__ b2, float* __restrict__ out, int N) {
    int w = (blockIdx.x * blockDim.x + threadIdx.x) >> 5;
    if (w >= N) return;
    int lane = threadIdx.x & 31;
    int c = lane & 15;
    int g = lane >> 4;        // two edges per iteration (half-warp each)
    float ed = g_e2d[w];
    int beg = g_off[w], end = g_off[w + 1];
    float acc = 0.f, dn = 0.f;
    for (int i = beg + g; i < end; i += 2) {
        int s = __ldg(&g_csr[i]);
        float t = __ldg(&g_e2s[s]) + ed;
        t = t > 0.f ? t : 0.2f * t;
        float wt = __expf(t);
        acc = fmaf(wt, __ldg(&g_h2[(size_t)s * OUT_CH + c]), acc);
        dn += wt;
    }
    acc += __shfl_xor_sync(0xffffffffu, acc, 16);
    dn  += __shfl_xor_sync(0xffffffffu, dn, 16);
    float v = acc / dn + b2[c];
    // log_softmax over the 16 channels (both half-warps hold identical copies)
    float m = v;
#pragma unroll
    for (int o = 8; o; o >>= 1) m = fmaxf(m, __shfl_xor_sync(0xffffffffu, m, o));
    float S = __expf(v - m);
#pragma unroll
    for (int o = 8; o; o >>= 1) S += __shfl_xor_sync(0xffffffffu, S, o);
    if (lane < 16) out[(size_t)w * OUT_CH + c] = (v - m) - __logf(S);
}

// ---------------- launch ----------------
extern "C" void kernel_launch(void* const* d_in, const int* in_sizes, int n_in,
                              void* d_out, int out_size)
{
    const float* x   = (const float*)d_in[0];
    const int*   ei  = (const int*)  d_in[1];
    const float* W1  = (const float*)d_in[2];
    const float* a1s = (const float*)d_in[3];
    const float* a1d = (const float*)d_in[4];
    const float* b1  = (const float*)d_in[5];
    const float* W2  = (const float*)d_in[6];
    const float* a2s = (const float*)d_in[7];
    const float* a2d = (const float*)d_in[8];
    const float* b2  = (const float*)d_in[9];
    float* out = (float*)d_out;

    int N      = in_sizes[0] / IN_CH;     // 100000
    int E_orig = in_sizes[1] / 2;         // 3200000
    int E_tot  = E_orig + N;

    // gemm1 kept at launch index 3 so the fixed ncu skip-count profiles it.
    k_zero   <<<(N + 255) / 256, 256>>>(N);
    k_deg    <<<(E_tot + 255) / 256, 256>>>(ei, E_orig, E_tot);
    k_scanA  <<<(N + 1023) / 1024, 1024>>>(N);
    k_gemm1  <<<(N + 127) / 128, 256>>>(x, W1, a1s, a1d, N);
    k_scanB  <<<1, 1>>>((N + 1023) / 1024);
    k_scanC  <<<(N + 255) / 256, 256>>>(N);
    k_cursor <<<(N + 255) / 256, 256>>>(N);
    k_scatter<<<(E_tot + 255) / 256, 256>>>(ei, E_orig, E_tot);

    // layer 1 aggregation
    k_edge1<<<(N * 32 + 255) / 256, 256>>>(b1, N);

    // layer 2 + fused log_softmax
    k_gemm2<<<(N + 63) / 64, 256>>>(W2, a2s, a2d, N);
    k_edge2<<<(N * 32 + 255) / 256, 256>>>(b2, out, N);
}